// round 13
// baseline (speedup 1.0000x reference)
#include <cuda_runtime.h>
#include <cstdint>

// Problem constants (fixed by setup_inputs): B=32, T_src=1024, H=512.
#define B_DIM 32
#define T_SRC 1024
#define H_DIM 512
#define ROWS 8             // output rows per block (16 KB contiguous output span)
#define ROW_BYTES (H_DIM * 4)   // 2048

// ---- minimal PTX helpers (local) ----
__device__ __forceinline__ uint32_t smem_u32(const void* p) {
    uint32_t a;
    asm("{ .reg .u64 t; cvta.to.shared.u64 t, %1; cvt.u32.u64 %0, t; }" : "=r"(a) : "l"(p));
    return a;
}
__device__ __forceinline__ void mbar_init(uint32_t mbar, uint32_t cnt) {
    asm volatile("mbarrier.init.shared.b64 [%0], %1;" :: "r"(mbar), "r"(cnt) : "memory");
}
__device__ __forceinline__ void mbar_expect_tx(uint32_t mbar, uint32_t bytes) {
    asm volatile("mbarrier.arrive.expect_tx.shared.b64 _, [%0], %1;" :: "r"(mbar), "r"(bytes) : "memory");
}
__device__ __forceinline__ void mbar_wait(uint32_t mbar, uint32_t parity) {
    asm volatile(
        "{\n\t"
        ".reg .pred P1;\n\t"
        "WAIT_LOOP_%=:\n\t"
        "mbarrier.try_wait.parity.acquire.cta.shared::cta.b64 P1, [%0], %1, 0x989680;\n\t"
        "@P1 bra.uni WAIT_DONE_%=;\n\t"
        "bra.uni WAIT_LOOP_%=;\n\t"
        "WAIT_DONE_%=:\n\t"
        "}" :: "r"(mbar), "r"(parity) : "memory");
}
// 1D bulk copy GMEM -> SMEM, completion via mbarrier complete_tx.
__device__ __forceinline__ void bulk_load_1d(uint32_t smem_dst, const void* gsrc,
                                             uint32_t bytes, uint32_t mbar) {
    asm volatile(
        "cp.async.bulk.shared::cluster.global.mbarrier::complete_tx::bytes [%0], [%1], %2, [%3];"
        :: "r"(smem_dst), "l"(gsrc), "r"(bytes), "r"(mbar) : "memory");
}
// 1D bulk copy SMEM -> GMEM with L2 evict_first (write-once stream; keep x resident).
__device__ __forceinline__ void bulk_store_1d(void* gdst, uint32_t smem_src, uint32_t bytes) {
    uint64_t pol;
    asm volatile("createpolicy.fractional.L2::evict_first.b64 %0, 1.0;" : "=l"(pol));
    asm volatile(
        "cp.async.bulk.global.shared::cta.bulk_group.L2::cache_hint [%0], [%1], %2, %3;"
        :: "l"(gdst), "r"(smem_src), "r"(bytes), "l"(pol) : "memory");
    asm volatile("cp.async.bulk.commit_group;" ::: "memory");
}
__device__ __forceinline__ void bulk_store_wait_read() {
    asm volatile("cp.async.bulk.wait_group.read 0;" ::: "memory");
}
__device__ __forceinline__ void fence_proxy_async_shared() {
    asm volatile("fence.proxy.async.shared::cta;" ::: "memory");
}

// SINGLE fused kernel: grid (ceil(max_len/8), B), 128 threads.
// Prologue: scan durations[b,:] into SMEM (proven R10 path), 8 searchsorted
// lookups. Body (NEW, DMA-driven): thread0 issues <=8 x 2KB cp.async.bulk
// gathers of the source rows into a 16KB SMEM tile (mbarrier expect_tx);
// pad rows zero-filled via STS; then ONE contiguous cp.async.bulk store of
// rows_here*2KB to the output (evict_first). Warp issue path carries almost
// no memory instructions; the DMA engines own the stream.
__global__ void __launch_bounds__(128) lr_fused_kernel(
    const float* __restrict__ x,
    const int*  __restrict__ dur,
    float* __restrict__ out,
    float* __restrict__ mask,
    int max_len)
{
    __shared__ __align__(128) float4 s_tile[ROWS * (H_DIM / 4)];  // 16 KB
    __shared__ int s_cum[T_SRC];
    __shared__ int s_wsum[4];
    __shared__ int s_idx[ROWS];
    __shared__ __align__(8) unsigned long long s_mbar;

    const int t0   = blockIdx.x * ROWS;
    const int b    = blockIdx.y;
    const int tid  = threadIdx.x;        // 0..127
    const int lane = tid & 31;
    const int wid  = tid >> 5;

    const uint32_t mbar = smem_u32(&s_mbar);
    if (tid == 0) mbar_init(mbar, 1);

    // ---- Prologue: scan durations[b, :] into s_cum ----
    {
        const int4* dr = reinterpret_cast<const int4*>(dur + b * T_SRC + tid * 8);
        int4 d0 = __ldg(&dr[0]);
        int4 d1 = __ldg(&dr[1]);
        int p0 = d0.x, p1 = p0 + d0.y, p2 = p1 + d0.z, p3 = p2 + d0.w;
        int p4 = p3 + d1.x, p5 = p4 + d1.y, p6 = p5 + d1.z, p7 = p6 + d1.w;

        int sc = p7;
#pragma unroll
        for (int off = 1; off < 32; off <<= 1) {
            int n = __shfl_up_sync(0xffffffffu, sc, off);
            if (lane >= off) sc += n;
        }
        if (lane == 31) s_wsum[wid] = sc;
        __syncthreads();

        int base = 0;
#pragma unroll
        for (int w = 0; w < 4; ++w) base += (w < wid) ? s_wsum[w] : 0;
        const int tb = base + sc - p7;

        int* c = s_cum + tid * 8;
        c[0] = tb + p0; c[1] = tb + p1; c[2] = tb + p2; c[3] = tb + p3;
        c[4] = tb + p4; c[5] = tb + p5; c[6] = tb + p6; c[7] = tb + p7;
    }
    __syncthreads();

    const int total = s_cum[T_SRC - 1];

    // ---- 8 searchsorted lookups (threads 0..7) ----
    if (tid < ROWS) {
        int t = t0 + tid;
        int idx = -1;
        if (t < max_len && t < total) {
            int lo = 0, hi = T_SRC;          // first s with cum[s] > t
            while (lo < hi) {
                int mid = (lo + hi) >> 1;
                if (s_cum[mid] <= t) lo = mid + 1; else hi = mid;
            }
            idx = lo < (T_SRC - 1) ? lo : (T_SRC - 1);
        }
        s_idx[tid] = idx;
    }
    __syncthreads();

    // All threads read row indices (uniform).
    int idx[ROWS];
#pragma unroll
    for (int r = 0; r < ROWS; ++r) idx[r] = s_idx[r];

    const int rows_here = (max_len - t0 < ROWS) ? (max_len - t0) : ROWS;
    int n_real = 0;
    bool has_pad = false;
#pragma unroll
    for (int r = 0; r < ROWS; ++r) {
        if (r < rows_here) {
            if (idx[r] >= 0) ++n_real; else has_pad = true;
        }
    }

    const float* __restrict__ xb = x + (size_t)b * T_SRC * H_DIM;
    float* __restrict__ ob = out + ((size_t)b * max_len + t0) * H_DIM;

    // Thread 0: issue DMA gathers for real rows.
    if (tid == 0 && n_real > 0) {
        mbar_expect_tx(mbar, (uint32_t)n_real * ROW_BYTES);
#pragma unroll
        for (int r = 0; r < ROWS; ++r) {
            if (idx[r] >= 0) {
                bulk_load_1d(smem_u32(&s_tile[r * (H_DIM / 4)]),
                             xb + (size_t)idx[r] * H_DIM,
                             ROW_BYTES, mbar);
            }
        }
    }

    // Zero-fill pad rows (STS.128 by all threads), fence generic->async.
    if (has_pad) {
#pragma unroll
        for (int r = 0; r < ROWS; ++r) {
            if (r < rows_here && idx[r] < 0)
                s_tile[r * (H_DIM / 4) + tid] = make_float4(0.f, 0.f, 0.f, 0.f);
        }
        fence_proxy_async_shared();
    }
    __syncthreads();

    // Thread 0: wait for gathers, then one contiguous bulk store.
    if (tid == 0) {
        if (n_real > 0) mbar_wait(mbar, 0);
        bulk_store_1d(ob, smem_u32(s_tile), (uint32_t)rows_here * ROW_BYTES);
        bulk_store_wait_read();
    }

    // Mask: lanes 0..ROWS-1 write one row each.
    if (tid < ROWS) {
        int t = t0 + tid;
        if (t < max_len)
            mask[(size_t)b * max_len + t] = (t >= total) ? 1.0f : 0.0f;
    }

    // No thread exits until thread0's store has finished reading SMEM.
    __syncthreads();
}

extern "C" void kernel_launch(void* const* d_in, const int* in_sizes, int n_in,
                              void* d_out, int out_size) {
    const float* x   = (const float*)d_in[0];
    const int*   dur = (const int*)d_in[1];
    float* out = (float*)d_out;

    // out_size = B*max_len*H + B*max_len = B*max_len*(H+1)
    const int max_len = out_size / (B_DIM * (H_DIM + 1));
    float* mask = out + (size_t)B_DIM * max_len * H_DIM;

    dim3 grid((max_len + ROWS - 1) / ROWS, B_DIM);
    lr_fused_kernel<<<grid, 128>>>(x, dur, out, mask, max_len);
}

// round 14
// speedup vs baseline: 1.0050x; 1.0050x over previous
#include <cuda_runtime.h>
#include <cstdint>

// Problem constants (fixed by setup_inputs): B=32, T_src=1024, H=512.
#define B_DIM 32
#define T_SRC 1024
#define H_DIM 512
#define ROWS 16            // output rows per block (32 KB contiguous output span)
#define ROW_BYTES (H_DIM * 4)   // 2048

// ---- minimal PTX helpers (local) ----
__device__ __forceinline__ uint32_t smem_u32(const void* p) {
    uint32_t a;
    asm("{ .reg .u64 t; cvta.to.shared.u64 t, %1; cvt.u32.u64 %0, t; }" : "=r"(a) : "l"(p));
    return a;
}
__device__ __forceinline__ void mbar_init(uint32_t mbar, uint32_t cnt) {
    asm volatile("mbarrier.init.shared.b64 [%0], %1;" :: "r"(mbar), "r"(cnt) : "memory");
}
__device__ __forceinline__ void mbar_expect_tx(uint32_t mbar, uint32_t bytes) {
    asm volatile("mbarrier.arrive.expect_tx.shared.b64 _, [%0], %1;" :: "r"(mbar), "r"(bytes) : "memory");
}
__device__ __forceinline__ void mbar_wait(uint32_t mbar, uint32_t parity) {
    asm volatile(
        "{\n\t"
        ".reg .pred P1;\n\t"
        "WAIT_LOOP_%=:\n\t"
        "mbarrier.try_wait.parity.acquire.cta.shared::cta.b64 P1, [%0], %1, 0x989680;\n\t"
        "@P1 bra.uni WAIT_DONE_%=;\n\t"
        "bra.uni WAIT_LOOP_%=;\n\t"
        "WAIT_DONE_%=:\n\t"
        "}" :: "r"(mbar), "r"(parity) : "memory");
}
// 1D bulk copy GMEM -> SMEM, completion via mbarrier complete_tx.
__device__ __forceinline__ void bulk_load_1d(uint32_t smem_dst, const void* gsrc,
                                             uint32_t bytes, uint32_t mbar) {
    asm volatile(
        "cp.async.bulk.shared::cluster.global.mbarrier::complete_tx::bytes [%0], [%1], %2, [%3];"
        :: "r"(smem_dst), "l"(gsrc), "r"(bytes), "r"(mbar) : "memory");
}
// 1D bulk copy SMEM -> GMEM with L2 evict_first (write-once stream; keep x resident).
__device__ __forceinline__ void bulk_store_1d(void* gdst, uint32_t smem_src, uint32_t bytes) {
    uint64_t pol;
    asm volatile("createpolicy.fractional.L2::evict_first.b64 %0, 1.0;" : "=l"(pol));
    asm volatile(
        "cp.async.bulk.global.shared::cta.bulk_group.L2::cache_hint [%0], [%1], %2, %3;"
        :: "l"(gdst), "r"(smem_src), "r"(bytes), "l"(pol) : "memory");
    asm volatile("cp.async.bulk.commit_group;" ::: "memory");
}
__device__ __forceinline__ void bulk_store_wait_read() {
    asm volatile("cp.async.bulk.wait_group.read 0;" ::: "memory");
}
__device__ __forceinline__ void fence_proxy_async_shared() {
    asm volatile("fence.proxy.async.shared::cta;" ::: "memory");
}

// SINGLE fused kernel: grid (ceil(max_len/16), B), 128 threads.
// R13 DMA body scaled to ROWS=16: payload is entirely DMA-issued (thread0),
// so doubling rows/block costs no registers and no warp issue (the R11
// failure mode does not apply). Halves block count -> prologue (scan +
// barriers + search) per output byte halves; one contiguous 32 KB bulk store
// per block. 128 threads only run the scan / zero-fill / mask.
__global__ void __launch_bounds__(128) lr_fused_kernel(
    const float* __restrict__ x,
    const int*  __restrict__ dur,
    float* __restrict__ out,
    float* __restrict__ mask,
    int max_len)
{
    __shared__ __align__(128) float4 s_tile[ROWS * (H_DIM / 4)];  // 32 KB
    __shared__ int s_cum[T_SRC];
    __shared__ int s_wsum[4];
    __shared__ int s_idx[ROWS];
    __shared__ __align__(8) unsigned long long s_mbar;

    const int t0   = blockIdx.x * ROWS;
    const int b    = blockIdx.y;
    const int tid  = threadIdx.x;        // 0..127
    const int lane = tid & 31;
    const int wid  = tid >> 5;

    const uint32_t mbar = smem_u32(&s_mbar);
    if (tid == 0) mbar_init(mbar, 1);

    // ---- Prologue: scan durations[b, :] into s_cum ----
    {
        const int4* dr = reinterpret_cast<const int4*>(dur + b * T_SRC + tid * 8);
        int4 d0 = __ldg(&dr[0]);
        int4 d1 = __ldg(&dr[1]);
        int p0 = d0.x, p1 = p0 + d0.y, p2 = p1 + d0.z, p3 = p2 + d0.w;
        int p4 = p3 + d1.x, p5 = p4 + d1.y, p6 = p5 + d1.z, p7 = p6 + d1.w;

        int sc = p7;
#pragma unroll
        for (int off = 1; off < 32; off <<= 1) {
            int n = __shfl_up_sync(0xffffffffu, sc, off);
            if (lane >= off) sc += n;
        }
        if (lane == 31) s_wsum[wid] = sc;
        __syncthreads();

        int base = 0;
#pragma unroll
        for (int w = 0; w < 4; ++w) base += (w < wid) ? s_wsum[w] : 0;
        const int tb = base + sc - p7;

        int* c = s_cum + tid * 8;
        c[0] = tb + p0; c[1] = tb + p1; c[2] = tb + p2; c[3] = tb + p3;
        c[4] = tb + p4; c[5] = tb + p5; c[6] = tb + p6; c[7] = tb + p7;
    }
    __syncthreads();

    const int total = s_cum[T_SRC - 1];

    // ---- 16 searchsorted lookups (threads 0..15) ----
    if (tid < ROWS) {
        int t = t0 + tid;
        int idx = -1;
        if (t < max_len && t < total) {
            int lo = 0, hi = T_SRC;          // first s with cum[s] > t
            while (lo < hi) {
                int mid = (lo + hi) >> 1;
                if (s_cum[mid] <= t) lo = mid + 1; else hi = mid;
            }
            idx = lo < (T_SRC - 1) ? lo : (T_SRC - 1);
        }
        s_idx[tid] = idx;
    }
    __syncthreads();

    // All threads read row indices (uniform).
    int idx[ROWS];
#pragma unroll
    for (int r = 0; r < ROWS; ++r) idx[r] = s_idx[r];

    const int rows_here = (max_len - t0 < ROWS) ? (max_len - t0) : ROWS;
    int n_real = 0;
    bool has_pad = false;
#pragma unroll
    for (int r = 0; r < ROWS; ++r) {
        if (r < rows_here) {
            if (idx[r] >= 0) ++n_real; else has_pad = true;
        }
    }

    const float* __restrict__ xb = x + (size_t)b * T_SRC * H_DIM;
    float* __restrict__ ob = out + ((size_t)b * max_len + t0) * H_DIM;

    // Thread 0: issue DMA gathers for real rows.
    if (tid == 0 && n_real > 0) {
        mbar_expect_tx(mbar, (uint32_t)n_real * ROW_BYTES);
#pragma unroll
        for (int r = 0; r < ROWS; ++r) {
            if (idx[r] >= 0) {
                bulk_load_1d(smem_u32(&s_tile[r * (H_DIM / 4)]),
                             xb + (size_t)idx[r] * H_DIM,
                             ROW_BYTES, mbar);
            }
        }
    }

    // Zero-fill pad rows (STS.128 by all threads), fence generic->async.
    if (has_pad) {
#pragma unroll
        for (int r = 0; r < ROWS; ++r) {
            if (r < rows_here && idx[r] < 0)
                s_tile[r * (H_DIM / 4) + tid] = make_float4(0.f, 0.f, 0.f, 0.f);
        }
        fence_proxy_async_shared();
    }
    __syncthreads();

    // Thread 0: wait for gathers, then one contiguous 32 KB bulk store.
    if (tid == 0) {
        if (n_real > 0) mbar_wait(mbar, 0);
        bulk_store_1d(ob, smem_u32(s_tile), (uint32_t)rows_here * ROW_BYTES);
        bulk_store_wait_read();
    }

    // Mask: threads 0..15 write one row each.
    if (tid < ROWS) {
        int t = t0 + tid;
        if (t < max_len)
            mask[(size_t)b * max_len + t] = (t >= total) ? 1.0f : 0.0f;
    }

    // No thread exits until thread0's store has finished reading SMEM.
    __syncthreads();
}

extern "C" void kernel_launch(void* const* d_in, const int* in_sizes, int n_in,
                              void* d_out, int out_size) {
    const float* x   = (const float*)d_in[0];
    const int*   dur = (const int*)d_in[1];
    float* out = (float*)d_out;

    // out_size = B*max_len*H + B*max_len = B*max_len*(H+1)
    const int max_len = out_size / (B_DIM * (H_DIM + 1));
    float* mask = out + (size_t)B_DIM * max_len * H_DIM;

    dim3 grid((max_len + ROWS - 1) / ROWS, B_DIM);
    lr_fused_kernel<<<grid, 128>>>(x, dur, out, mask, max_len);
}